// round 4
// baseline (speedup 1.0000x reference)
#include <cuda_runtime.h>

#define HID   128
#define NB    16
#define NPTS  10000
#define OUTD  5
#define LTOT  (NB * NPTS)      // 160000 points
#define BP    128              // points per block
#define XCOLS 256              // dup: 2 floats per point
#define WSTRIDE 132            // weight smem stride (floats)

// Scratch (device globals — no allocation allowed)
__device__ float g_gate[4 * NB * HID];   // gates per layer/batch/feature
__device__ float g_M[NB * HID * 8];      // folded gate3*(Wtf@bc^T), padded 8/[b,g]
__device__ float g_c[NB * 8];            // folded btf·bc

typedef unsigned long long u64;

__device__ __forceinline__ u64 pack2(float lo, float hi) {
    u64 r; asm("mov.b64 %0, {%1, %2};" : "=l"(r) : "f"(lo), "f"(hi)); return r;
}
__device__ __forceinline__ void unpack2(u64 v, float& lo, float& hi) {
    asm("mov.b64 {%0, %1}, %2;" : "=f"(lo), "=f"(hi) : "l"(v));
}
__device__ __forceinline__ void ffma2(u64& d, u64 a, u64 b) {
    asm("fma.rn.f32x2 %0, %1, %2, %0;" : "+l"(d) : "l"(a), "l"(b));
}
__device__ __forceinline__ float rowdy_f(float t, float a, float w) {
    float th; asm("tanh.approx.f32 %0, %1;" : "=f"(th) : "f"(t));
    return th + a * __sinf(w * t);
}
__device__ __forceinline__ void cp_async16(void* smem_dst, const void* gmem_src) {
    unsigned sm = (unsigned)__cvta_generic_to_shared(smem_dst);
    asm volatile("cp.async.cg.shared.global [%0], [%1], 16;" :: "r"(sm), "l"(gmem_src));
}

// ---------------------------------------------------------------------------
// Kernel 1: branch MLP, gates, folded final matrices. grid=16, block=512.
// ---------------------------------------------------------------------------
__global__ void __launch_bounds__(512, 1) branch_kernel(
    const float* __restrict__ params, const float* __restrict__ Wb0,
    const float* __restrict__ bb0,    const float* __restrict__ Wb,
    const float* __restrict__ bb,     const float* __restrict__ Wbf,
    const float* __restrict__ bbf,    const float* __restrict__ ab,
    const float* __restrict__ wb,     const float* __restrict__ Wtf,
    const float* __restrict__ btf)
{
    const int b   = blockIdx.x;
    const int tid = threadIdx.x;
    const int j   = tid & 127;
    const int q   = tid >> 7;            // 0..3, k-range split

    __shared__ float sh_h[HID];
    __shared__ float sh_part[4 * HID];
    __shared__ float sh_bc[OUTD][HID];
    __shared__ float sh_p[8];

    if (tid < 6) sh_p[tid] = params[b * 6 + tid];
    __syncthreads();

    float h = 0.f, gate = 0.f;           // live only in q==0
    if (q == 0) {
        float t = bb0[j];
#pragma unroll
        for (int k = 0; k < 6; k++) t += sh_p[k] * Wb0[k * HID + j];
        h = rowdy_f(t, ab[j], wb[j]);
        gate = h;
        sh_h[j] = h;
        g_gate[(0 * NB + b) * HID + j] = gate;
    }
    __syncthreads();

    for (int i = 0; i < 3; i++) {
        const float* W = Wb + i * HID * HID;
        float tp = 0.f;
#pragma unroll 8
        for (int k = q * 32; k < q * 32 + 32; k++) tp += sh_h[k] * W[k * HID + j];
        sh_part[q * HID + j] = tp;
        __syncthreads();
        if (q == 0) {
            float t2 = bb[i * HID + j] + sh_part[j] + sh_part[HID + j]
                     + sh_part[2 * HID + j] + sh_part[3 * HID + j];
            h = rowdy_f(t2, ab[(i + 1) * HID + j], wb[(i + 1) * HID + j]);
            sh_h[j] = h;
            gate += h;
            g_gate[((i + 1) * NB + b) * HID + j] = gate;
        }
        __syncthreads();
    }
    // gate (q==0) is now gate3[b][j]

    // branch_out -> sh_bc[o][j], k-split
    {
        float tb[OUTD] = {0.f, 0.f, 0.f, 0.f, 0.f};
#pragma unroll 4
        for (int k = q * 32; k < q * 32 + 32; k++) {
            float hv = sh_h[k];
#pragma unroll
            for (int o = 0; o < OUTD; o++)
                tb[o] += hv * Wbf[k * (HID * OUTD) + o * HID + j];
        }
#pragma unroll
        for (int o = 0; o < OUTD; o++) {
            sh_part[q * HID + j] = tb[o];
            __syncthreads();
            if (q == 0)
                sh_bc[o][j] = bbf[o * HID + j] + sh_part[j] + sh_part[HID + j]
                            + sh_part[2 * HID + j] + sh_part[3 * HID + j];
            __syncthreads();
        }
    }

    // M'[b][g][o] = gate3[g] * sum_h Wtf[g][h]*bc[o][h]
    {
        float am[OUTD] = {0.f, 0.f, 0.f, 0.f, 0.f};
#pragma unroll 4
        for (int hh = q * 32; hh < q * 32 + 32; hh++) {
            float w = __ldg(&Wtf[j * HID + hh]);
#pragma unroll
            for (int o = 0; o < OUTD; o++) am[o] += w * sh_bc[o][hh];
        }
#pragma unroll
        for (int o = 0; o < OUTD; o++) {
            sh_part[q * HID + j] = am[o];
            __syncthreads();
            if (q == 0)
                g_M[(b * HID + j) * 8 + o] = gate *
                    (sh_part[j] + sh_part[HID + j] + sh_part[2 * HID + j] + sh_part[3 * HID + j]);
            __syncthreads();
        }
        if (q == 0) { g_M[(b * HID + j) * 8 + 5] = 0.f;
                      g_M[(b * HID + j) * 8 + 6] = 0.f;
                      g_M[(b * HID + j) * 8 + 7] = 0.f; }
    }
    if (tid < OUTD) {
        float c = 0.f;
#pragma unroll 8
        for (int hh = 0; hh < HID; hh++) c += btf[hh] * sh_bc[tid][hh];
        g_c[b * 8 + tid] = c;
    }
    if (tid >= OUTD && tid < 8) g_c[b * 8 + tid] = 0.f;
}

// ---------------------------------------------------------------------------
// Kernel 2: fused trunk. Block = 128 points x 128 features, 512 threads,
// 4x8 tile. Activations stored DUPLICATED (v,v) so FFMA2 splat operands load
// straight from SMEM — zero pack MOVs in the inner loop.
// ---------------------------------------------------------------------------
extern "C" __global__ void __launch_bounds__(512, 1)
trunk_kernel(const float* __restrict__ coords, const float* __restrict__ sdf,
             const float* __restrict__ Wt0,    const float* __restrict__ bt0,
             const float* __restrict__ Wt,     const float* __restrict__ bt,
             const float* __restrict__ at,     const float* __restrict__ wt,
             float* __restrict__ out)
{
    extern __shared__ float smem[];
    float* Xs = smem;                       // [128][XCOLS] dup activations
    float* Ws = smem + HID * XCOLS;         // [128][WSTRIDE] weights

    const int tid    = threadIdx.x;
    const int tx     = tid & 15;            // feature group
    const int ty     = tid >> 4;            // 0..31 point group
    const int p0     = blockIdx.x * BP;
    const int j0     = tx * 4;
    const int pbase  = ty * 4;
    const int colbase = 2 * pbase;
    const int swzT   = (tx & 3) << 3;       // store swizzle (same for all 8 rows)
    const int bstart = p0 / NPTS;
    const int bound  = (bstart + 1) * NPTS - p0;

    // kick off layer-1 weight staging
#pragma unroll
    for (int i = 0; i < 8; i++) {
        int idx = tid + i * 512;
        int r = idx >> 5, c = (idx & 31) * 4;
        cp_async16(&Ws[r * WSTRIDE + c], &((const float4*)Wt)[idx]);
    }
    asm volatile("cp.async.commit_group;");

    int jcol[8];
#pragma unroll
    for (int i = 0; i < 4; i++) { jcol[i] = j0 + i; jcol[i + 4] = 64 + j0 + i; }
    int bidx[4];
#pragma unroll
    for (int i = 0; i < 4; i++) bidx[i] = (pbase + i < bound) ? bstart : bstart + 1;

    // ---- layer 0 ----
    {
        float w0[8][4], btv[8], av[8], wv[8];
#pragma unroll
        for (int jj = 0; jj < 8; jj++) {
            int j = jcol[jj];
#pragma unroll
            for (int k = 0; k < 4; k++) w0[jj][k] = __ldg(&Wt0[k * HID + j]);
            btv[jj] = __ldg(&bt0[j]);
            av[jj]  = __ldg(&at[j]);
            wv[jj]  = __ldg(&wt[j]);
        }
        float val[8][4];
#pragma unroll
        for (int pp = 0; pp < 4; pp++) {
            int gp = p0 + pbase + pp;
            float c0 = coords[gp * 3 + 0];
            float c1 = coords[gp * 3 + 1];
            float c2 = coords[gp * 3 + 2];
            float c3 = sdf[gp];
            const float* grow = &g_gate[(0 * NB + bidx[pp]) * HID];
#pragma unroll
            for (int jj = 0; jj < 8; jj++) {
                float s = btv[jj];
                s += c0 * w0[jj][0]; s += c1 * w0[jj][1];
                s += c2 * w0[jj][2]; s += c3 * w0[jj][3];
                val[jj][pp] = rowdy_f(s, av[jj], wv[jj]) * __ldg(&grow[jcol[jj]]);
            }
        }
#pragma unroll
        for (int jj = 0; jj < 8; jj++) {
            ulonglong2* dst = (ulonglong2*)&Xs[jcol[jj] * XCOLS + (colbase ^ swzT)];
            ulonglong2 s0, s1;
            s0.x = pack2(val[jj][0], val[jj][0]); s0.y = pack2(val[jj][1], val[jj][1]);
            s1.x = pack2(val[jj][2], val[jj][2]); s1.y = pack2(val[jj][3], val[jj][3]);
            dst[0] = s0; dst[1] = s1;
        }
    }
    asm volatile("cp.async.wait_group 0;");
    __syncthreads();

    // ---- layers 1..3 ----
    for (int l = 1; l < 4; l++) {
        u64 acc[4][4];
#pragma unroll
        for (int pp = 0; pp < 4; pp++)
#pragma unroll
            for (int jp = 0; jp < 4; jp++) acc[pp][jp] = 0ull;

        for (int k0 = 0; k0 < HID; k0 += 8) {
#pragma unroll
            for (int kk = 0; kk < 8; kk++) {
                int k = k0 + kk;
                int c = colbase ^ (((k >> 2) & 3) << 3);
                const ulonglong2* ap = (const ulonglong2*)&Xs[k * XCOLS + c];
                ulonglong2 A01 = ap[0];          // (p0,p0),(p1,p1)
                ulonglong2 A23 = ap[1];          // (p2,p2),(p3,p3)
                ulonglong2 b0v = *(const ulonglong2*)&Ws[k * WSTRIDE + j0];
                ulonglong2 b1v = *(const ulonglong2*)&Ws[k * WSTRIDE + 64 + j0];
                ffma2(acc[0][0], A01.x, b0v.x); ffma2(acc[0][1], A01.x, b0v.y);
                ffma2(acc[0][2], A01.x, b1v.x); ffma2(acc[0][3], A01.x, b1v.y);
                ffma2(acc[1][0], A01.y, b0v.x); ffma2(acc[1][1], A01.y, b0v.y);
                ffma2(acc[1][2], A01.y, b1v.x); ffma2(acc[1][3], A01.y, b1v.y);
                ffma2(acc[2][0], A23.x, b0v.x); ffma2(acc[2][1], A23.x, b0v.y);
                ffma2(acc[2][2], A23.x, b1v.x); ffma2(acc[2][3], A23.x, b1v.y);
                ffma2(acc[3][0], A23.y, b0v.x); ffma2(acc[3][1], A23.y, b0v.y);
                ffma2(acc[3][2], A23.y, b1v.x); ffma2(acc[3][3], A23.y, b1v.y);
            }
        }
        __syncthreads();                      // all Xs/Ws reads done

        // stage next layer's weights while epilogue runs
        if (l < 3) {
#pragma unroll
            for (int i = 0; i < 8; i++) {
                int idx = tid + i * 512;
                int r = idx >> 5, c = (idx & 31) * 4;
                cp_async16(&Ws[r * WSTRIDE + c],
                           &((const float4*)(Wt + l * HID * HID))[idx]);
            }
            asm volatile("cp.async.commit_group;");
        }

        // epilogue: rowdy (+ gate for l<3; gate3 folded into M'), dup store
        const float* bvec = bt + (l - 1) * HID;
        float val[8][4];
#pragma unroll
        for (int jp = 0; jp < 4; jp++) {
            int jjlo = jp * 2;                       // feature index within tile
            int jlo  = jcol[jjlo], jhi = jcol[jjlo + 1];
            float btl = __ldg(&bvec[jlo]), bth = __ldg(&bvec[jhi]);
            float avl = __ldg(&at[l * HID + jlo]), avh = __ldg(&at[l * HID + jhi]);
            float wvl = __ldg(&wt[l * HID + jlo]), wvh = __ldg(&wt[l * HID + jhi]);
#pragma unroll
            for (int pp = 0; pp < 4; pp++) {
                float flo, fhi;
                unpack2(acc[pp][jp], flo, fhi);
                float r0 = rowdy_f(flo + btl, avl, wvl);
                float r1 = rowdy_f(fhi + bth, avh, wvh);
                if (l < 3) {
                    const float* grow = &g_gate[(l * NB + bidx[pp]) * HID];
                    r0 *= __ldg(&grow[jlo]);
                    r1 *= __ldg(&grow[jhi]);
                }
                val[jjlo][pp] = r0; val[jjlo + 1][pp] = r1;
            }
        }
#pragma unroll
        for (int jj = 0; jj < 8; jj++) {
            ulonglong2* dst = (ulonglong2*)&Xs[jcol[jj] * XCOLS + (colbase ^ swzT)];
            ulonglong2 s0, s1;
            s0.x = pack2(val[jj][0], val[jj][0]); s0.y = pack2(val[jj][1], val[jj][1]);
            s1.x = pack2(val[jj][2], val[jj][2]); s1.y = pack2(val[jj][3], val[jj][3]);
            dst[0] = s0; dst[1] = s1;
        }
        if (l < 3) asm volatile("cp.async.wait_group 0;");
        __syncthreads();
    }

    // ---- folded final: out[p][o] = c[b][o] + sum_g Xs[g][2p] * M'[b][g][o] ----
    {
        float* part = Ws;                     // reuse: [5][4][128]
        const int p = tid & 127;
        const int q = tid >> 7;               // 0..3, each sums 32 g's
        const int b = (p < bound) ? bstart : bstart + 1;
        float o0 = 0.f, o1 = 0.f, o2 = 0.f, o3 = 0.f, o4 = 0.f;
        const float4* Mb = (const float4*)&g_M[b * HID * 8];
#pragma unroll 8
        for (int g = q * 32; g < q * 32 + 32; g++) {
            float v   = Xs[g * XCOLS + ((2 * p) ^ (((g >> 2) & 3) << 3))];
            float4 m0 = __ldg(&Mb[g * 2 + 0]);
            float4 m1 = __ldg(&Mb[g * 2 + 1]);
            o0 += v * m0.x; o1 += v * m0.y; o2 += v * m0.z; o3 += v * m0.w;
            o4 += v * m1.x;
        }
        part[(0 * 4 + q) * 128 + p] = o0;
        part[(1 * 4 + q) * 128 + p] = o1;
        part[(2 * 4 + q) * 128 + p] = o2;
        part[(3 * 4 + q) * 128 + p] = o3;
        part[(4 * 4 + q) * 128 + p] = o4;
        __syncthreads();
        if (tid < BP) {
            const int pp2 = tid;
            const int gp2 = p0 + pp2;
            const int b2  = (pp2 < bound) ? bstart : bstart + 1;
            float* op = out + (size_t)gp2 * OUTD;
#pragma unroll
            for (int o = 0; o < OUTD; o++)
                op[o] = g_c[b2 * 8 + o]
                      + part[(o * 4 + 0) * 128 + pp2]
                      + part[(o * 4 + 1) * 128 + pp2]
                      + part[(o * 4 + 2) * 128 + pp2]
                      + part[(o * 4 + 3) * 128 + pp2];
        }
    }
}

// ---------------------------------------------------------------------------
extern "C" void kernel_launch(void* const* d_in, const int* in_sizes, int n_in,
                              void* d_out, int out_size)
{
    const float* coords = (const float*)d_in[0];
    const float* sdf    = (const float*)d_in[1];
    const float* params = (const float*)d_in[2];
    const float* Wb0    = (const float*)d_in[3];
    const float* bb0    = (const float*)d_in[4];
    const float* Wb     = (const float*)d_in[5];
    const float* bb     = (const float*)d_in[6];
    const float* Wbf    = (const float*)d_in[7];
    const float* bbf    = (const float*)d_in[8];
    const float* ab     = (const float*)d_in[9];
    const float* wb     = (const float*)d_in[10];
    const float* Wt0    = (const float*)d_in[11];
    const float* bt0    = (const float*)d_in[12];
    const float* Wt     = (const float*)d_in[13];
    const float* bt     = (const float*)d_in[14];
    const float* Wtf    = (const float*)d_in[15];
    const float* btf    = (const float*)d_in[16];
    const float* at     = (const float*)d_in[17];
    const float* wt     = (const float*)d_in[18];
    float* out = (float*)d_out;

    static int smem_set = 0;
    const int smem_bytes = (HID * XCOLS + HID * WSTRIDE) * sizeof(float); // 198656
    if (!smem_set) {
        cudaFuncSetAttribute(trunk_kernel,
                             cudaFuncAttributeMaxDynamicSharedMemorySize,
                             smem_bytes);
        smem_set = 1;
    }

    branch_kernel<<<NB, 512>>>(params, Wb0, bb0, Wb, bb, Wbf, bbf, ab, wb,
                               Wtf, btf);
    trunk_kernel<<<LTOT / BP, 512, smem_bytes>>>(coords, sdf, Wt0, bt0,
                                                 Wt, bt, at, wt, out);
}

// round 5
// speedup vs baseline: 1.2422x; 1.2422x over previous
#include <cuda_runtime.h>

#define HID   128
#define NB    16
#define NPTS  10000
#define OUTD  5
#define LTOT  (NB * NPTS)      // 160000 points
#define BP    128              // points per block
#define XSTRIDE 132            // Xs row stride (floats)
#define WSTRIDE 132            // Ws row stride (floats)
#define WROWS 64               // half-K weight staging

// Scratch (device globals — no allocation allowed)
__device__ float g_gate[4 * NB * HID];   // gates per layer/batch/feature
__device__ float g_M[NB * HID * 8];      // folded gate3*(Wtf@bc^T), padded 8/[b,g]
__device__ float g_c[NB * 8];            // folded btf·bc

typedef unsigned long long u64;

__device__ __forceinline__ u64 pack2(float lo, float hi) {
    u64 r; asm("mov.b64 %0, {%1, %2};" : "=l"(r) : "f"(lo), "f"(hi)); return r;
}
__device__ __forceinline__ void unpack2(u64 v, float& lo, float& hi) {
    asm("mov.b64 {%0, %1}, %2;" : "=f"(lo), "=f"(hi) : "l"(v));
}
__device__ __forceinline__ void ffma2(u64& d, u64 a, u64 b) {
    asm("fma.rn.f32x2 %0, %1, %2, %0;" : "+l"(d) : "l"(a), "l"(b));
}
__device__ __forceinline__ float rowdy_f(float t, float a, float w) {
    float th; asm("tanh.approx.f32 %0, %1;" : "=f"(th) : "f"(t));
    return th + a * __sinf(w * t);
}
// swizzled float offset into Xs[k][p]; XOR p bits[2:4] with k bits[2:4]
__device__ __forceinline__ int xswz(int k, int p) {
    return k * XSTRIDE + (p ^ (((k >> 2) & 7) << 2));
}
__device__ __forceinline__ void cp_async16(void* smem_dst, const void* gmem_src) {
    unsigned sm = (unsigned)__cvta_generic_to_shared(smem_dst);
    asm volatile("cp.async.cg.shared.global [%0], [%1], 16;" :: "r"(sm), "l"(gmem_src));
}

// ---------------------------------------------------------------------------
// Kernel 1: branch MLP, gates, folded final matrices. grid=16, block=512.
// ---------------------------------------------------------------------------
__global__ void __launch_bounds__(512, 1) branch_kernel(
    const float* __restrict__ params, const float* __restrict__ Wb0,
    const float* __restrict__ bb0,    const float* __restrict__ Wb,
    const float* __restrict__ bb,     const float* __restrict__ Wbf,
    const float* __restrict__ bbf,    const float* __restrict__ ab,
    const float* __restrict__ wb,     const float* __restrict__ Wtf,
    const float* __restrict__ btf)
{
    const int b   = blockIdx.x;
    const int tid = threadIdx.x;
    const int j   = tid & 127;
    const int q   = tid >> 7;            // 0..3, k-range split

    __shared__ float sh_h[HID];
    __shared__ float sh_part[4 * HID];
    __shared__ float sh_bc[OUTD][HID];
    __shared__ float sh_p[8];

    if (tid < 6) sh_p[tid] = params[b * 6 + tid];
    __syncthreads();

    float h = 0.f, gate = 0.f;           // live only in q==0
    if (q == 0) {
        float t = bb0[j];
#pragma unroll
        for (int k = 0; k < 6; k++) t += sh_p[k] * Wb0[k * HID + j];
        h = rowdy_f(t, ab[j], wb[j]);
        gate = h;
        sh_h[j] = h;
        g_gate[(0 * NB + b) * HID + j] = gate;
    }
    __syncthreads();

    for (int i = 0; i < 3; i++) {
        const float* W = Wb + i * HID * HID;
        float tp = 0.f;
#pragma unroll 8
        for (int k = q * 32; k < q * 32 + 32; k++) tp += sh_h[k] * W[k * HID + j];
        sh_part[q * HID + j] = tp;
        __syncthreads();
        if (q == 0) {
            float t2 = bb[i * HID + j] + sh_part[j] + sh_part[HID + j]
                     + sh_part[2 * HID + j] + sh_part[3 * HID + j];
            h = rowdy_f(t2, ab[(i + 1) * HID + j], wb[(i + 1) * HID + j]);
            sh_h[j] = h;
            gate += h;
            g_gate[((i + 1) * NB + b) * HID + j] = gate;
        }
        __syncthreads();
    }
    // gate (q==0) is now gate3[b][j]

    // branch_out -> sh_bc[o][j], k-split
    {
        float tb[OUTD] = {0.f, 0.f, 0.f, 0.f, 0.f};
#pragma unroll 4
        for (int k = q * 32; k < q * 32 + 32; k++) {
            float hv = sh_h[k];
#pragma unroll
            for (int o = 0; o < OUTD; o++)
                tb[o] += hv * Wbf[k * (HID * OUTD) + o * HID + j];
        }
#pragma unroll
        for (int o = 0; o < OUTD; o++) {
            sh_part[q * HID + j] = tb[o];
            __syncthreads();
            if (q == 0)
                sh_bc[o][j] = bbf[o * HID + j] + sh_part[j] + sh_part[HID + j]
                            + sh_part[2 * HID + j] + sh_part[3 * HID + j];
            __syncthreads();
        }
    }

    // M'[b][g][o] = gate3[g] * sum_h Wtf[g][h]*bc[o][h]
    {
        float am[OUTD] = {0.f, 0.f, 0.f, 0.f, 0.f};
#pragma unroll 4
        for (int hh = q * 32; hh < q * 32 + 32; hh++) {
            float w = __ldg(&Wtf[j * HID + hh]);
#pragma unroll
            for (int o = 0; o < OUTD; o++) am[o] += w * sh_bc[o][hh];
        }
#pragma unroll
        for (int o = 0; o < OUTD; o++) {
            sh_part[q * HID + j] = am[o];
            __syncthreads();
            if (q == 0)
                g_M[(b * HID + j) * 8 + o] = gate *
                    (sh_part[j] + sh_part[HID + j] + sh_part[2 * HID + j] + sh_part[3 * HID + j]);
            __syncthreads();
        }
        if (q == 0) { g_M[(b * HID + j) * 8 + 5] = 0.f;
                      g_M[(b * HID + j) * 8 + 6] = 0.f;
                      g_M[(b * HID + j) * 8 + 7] = 0.f; }
    }
    if (tid < OUTD) {
        float c = 0.f;
#pragma unroll 8
        for (int hh = 0; hh < HID; hh++) c += btf[hh] * sh_bc[tid][hh];
        g_c[b * 8 + tid] = c;
    }
    if (tid >= OUTD && tid < 8) g_c[b * 8 + tid] = 0.f;
}

// stage 64 weight rows (rows_base offset into a [128][128] layer) into Ws
__device__ __forceinline__ void stage_half(float* Ws, const float* Wrows, int tid) {
    const float4* src = (const float4*)Wrows;     // 2048 float4 = 64x128 floats
#pragma unroll
    for (int i = 0; i < 4; i++) {
        int idx = tid + i * 512;
        int r = idx >> 5, c = (idx & 31) * 4;
        cp_async16(&Ws[r * WSTRIDE + c], &src[idx]);
    }
}

// ---------------------------------------------------------------------------
// Kernel 2: fused trunk. Block = 128 points x 128 features, 512 threads,
// 4x8 tile, packed f32x2 FMAs. Half-K weight staging (64 rows) keeps dynamic
// smem at 99KB so TWO blocks co-reside per SM (32 warps).
// ---------------------------------------------------------------------------
extern "C" __global__ void __launch_bounds__(512, 2)
trunk_kernel(const float* __restrict__ coords, const float* __restrict__ sdf,
             const float* __restrict__ Wt0,    const float* __restrict__ bt0,
             const float* __restrict__ Wt,     const float* __restrict__ bt,
             const float* __restrict__ at,     const float* __restrict__ wt,
             float* __restrict__ out)
{
    extern __shared__ float smem[];
    float* Xs = smem;                       // [128][XSTRIDE] activations
    float* Ws = smem + HID * XSTRIDE;       // [WROWS][WSTRIDE] half weights

    const int tid    = threadIdx.x;
    const int tx     = tid & 15;            // feature group
    const int ty     = tid >> 4;            // 0..31 point group
    const int p0     = blockIdx.x * BP;
    const int j0     = tx * 4;
    const int pbase  = ty * 4;
    const int bstart = p0 / NPTS;
    const int bound  = (bstart + 1) * NPTS - p0;

    // stage layer-1 first half immediately
    stage_half(Ws, Wt, tid);
    asm volatile("cp.async.commit_group;");

    int jcol[8];
#pragma unroll
    for (int i = 0; i < 4; i++) { jcol[i] = j0 + i; jcol[i + 4] = 64 + j0 + i; }
    int bidx[4];
#pragma unroll
    for (int i = 0; i < 4; i++) bidx[i] = (pbase + i < bound) ? bstart : bstart + 1;

    // ---- layer 0: (coords,sdf) 4 -> 128 ----
    {
        float in4[4][4];
#pragma unroll
        for (int pp = 0; pp < 4; pp++) {
            int gp = p0 + pbase + pp;
            in4[pp][0] = coords[gp * 3 + 0];
            in4[pp][1] = coords[gp * 3 + 1];
            in4[pp][2] = coords[gp * 3 + 2];
            in4[pp][3] = sdf[gp];
        }
#pragma unroll
        for (int jj = 0; jj < 8; jj++) {
            int j = jcol[jj];
            float w0 = __ldg(&Wt0[0 * HID + j]);
            float w1 = __ldg(&Wt0[1 * HID + j]);
            float w2 = __ldg(&Wt0[2 * HID + j]);
            float w3 = __ldg(&Wt0[3 * HID + j]);
            float btv = __ldg(&bt0[j]);
            float av  = __ldg(&at[j]);
            float wv  = __ldg(&wt[j]);
            float v[4];
#pragma unroll
            for (int pp = 0; pp < 4; pp++) {
                float s = btv;
                s += in4[pp][0] * w0; s += in4[pp][1] * w1;
                s += in4[pp][2] * w2; s += in4[pp][3] * w3;
                float g = __ldg(&g_gate[(0 * NB + bidx[pp]) * HID + j]);
                v[pp] = rowdy_f(s, av, wv) * g;
            }
            *(float4*)&Xs[xswz(j, pbase)] = make_float4(v[0], v[1], v[2], v[3]);
        }
    }
    asm volatile("cp.async.wait_group 0;");
    __syncthreads();

    // ---- layers 1..3 ----
    for (int l = 1; l < 4; l++) {
        const float* Wl = Wt + (l - 1) * HID * HID;
        u64 acc[4][4];
#pragma unroll
        for (int pp = 0; pp < 4; pp++)
#pragma unroll
            for (int jp = 0; jp < 4; jp++) acc[pp][jp] = 0ull;

        // two half-K passes; Ws holds rows [h*64, h*64+64)
#pragma unroll
        for (int h = 0; h < 2; h++) {
#pragma unroll 8
            for (int kk = 0; kk < WROWS; kk++) {
                int k = h * WROWS + kk;
                float4 a4 = *(const float4*)&Xs[xswz(k, pbase)];
                ulonglong2 b0 = *(const ulonglong2*)&Ws[kk * WSTRIDE + j0];
                ulonglong2 b1 = *(const ulonglong2*)&Ws[kk * WSTRIDE + 64 + j0];
                u64 s0 = pack2(a4.x, a4.x), s1 = pack2(a4.y, a4.y);
                u64 s2 = pack2(a4.z, a4.z), s3 = pack2(a4.w, a4.w);
                ffma2(acc[0][0], s0, b0.x); ffma2(acc[0][1], s0, b0.y);
                ffma2(acc[0][2], s0, b1.x); ffma2(acc[0][3], s0, b1.y);
                ffma2(acc[1][0], s1, b0.x); ffma2(acc[1][1], s1, b0.y);
                ffma2(acc[1][2], s1, b1.x); ffma2(acc[1][3], s1, b1.y);
                ffma2(acc[2][0], s2, b0.x); ffma2(acc[2][1], s2, b0.y);
                ffma2(acc[2][2], s2, b1.x); ffma2(acc[2][3], s2, b1.y);
                ffma2(acc[3][0], s3, b0.x); ffma2(acc[3][1], s3, b0.y);
                ffma2(acc[3][2], s3, b1.x); ffma2(acc[3][3], s3, b1.y);
            }
            __syncthreads();                  // Ws reads of this half done
            if (h == 0) {                     // stage second half
                stage_half(Ws, Wl + WROWS * HID, tid);
                asm volatile("cp.async.commit_group;");
                asm volatile("cp.async.wait_group 0;");
                __syncthreads();
            }
        }
        // here: all Xs reads for this layer done (barrier after h=1 loop is
        // the one below, so put it now before epilogue writes Xs)
        // stage next layer's first half; overlaps epilogue
        if (l < 3) {
            stage_half(Ws, Wt + l * HID * HID, tid);
            asm volatile("cp.async.commit_group;");
        }

        // epilogue: rowdy (+ gate for l<3; gate3 folded into M'), transposed
        const float* bvec = bt + (l - 1) * HID;
#pragma unroll
        for (int jp = 0; jp < 4; jp++) {
            int jjlo = jp * 2;
            int jlo  = jcol[jjlo], jhi = jcol[jjlo + 1];
            float btl = __ldg(&bvec[jlo]), bth = __ldg(&bvec[jhi]);
            float avl = __ldg(&at[l * HID + jlo]), avh = __ldg(&at[l * HID + jhi]);
            float wvl = __ldg(&wt[l * HID + jlo]), wvh = __ldg(&wt[l * HID + jhi]);
            float r0[4], r1[4];
#pragma unroll
            for (int pp = 0; pp < 4; pp++) {
                float flo, fhi;
                unpack2(acc[pp][jp], flo, fhi);
                r0[pp] = rowdy_f(flo + btl, avl, wvl);
                r1[pp] = rowdy_f(fhi + bth, avh, wvh);
                if (l < 3) {
                    const float* grow = &g_gate[(l * NB + bidx[pp]) * HID];
                    r0[pp] *= __ldg(&grow[jlo]);
                    r1[pp] *= __ldg(&grow[jhi]);
                }
            }
            *(float4*)&Xs[xswz(jlo, pbase)] = make_float4(r0[0], r0[1], r0[2], r0[3]);
            *(float4*)&Xs[xswz(jhi, pbase)] = make_float4(r1[0], r1[1], r1[2], r1[3]);
        }
        if (l < 3) asm volatile("cp.async.wait_group 0;");
        __syncthreads();
    }

    // ---- folded final: out[p][o] = c[b][o] + sum_g Xs[g][p] * M'[b][g][o] ----
    {
        float* part = Ws;                     // reuse: [5][4][128] = 2560 floats
        const int p = tid & 127;
        const int q = tid >> 7;               // 0..3, each sums 32 g's
        const int b = (p < bound) ? bstart : bstart + 1;
        float o0 = 0.f, o1 = 0.f, o2 = 0.f, o3 = 0.f, o4 = 0.f;
        const float4* Mb = (const float4*)&g_M[b * HID * 8];
#pragma unroll 8
        for (int g = q * 32; g < q * 32 + 32; g++) {
            float v   = Xs[xswz(g, p)];
            float4 m0 = __ldg(&Mb[g * 2 + 0]);
            float4 m1 = __ldg(&Mb[g * 2 + 1]);
            o0 += v * m0.x; o1 += v * m0.y; o2 += v * m0.z; o3 += v * m0.w;
            o4 += v * m1.x;
        }
        part[(0 * 4 + q) * 128 + p] = o0;
        part[(1 * 4 + q) * 128 + p] = o1;
        part[(2 * 4 + q) * 128 + p] = o2;
        part[(3 * 4 + q) * 128 + p] = o3;
        part[(4 * 4 + q) * 128 + p] = o4;
        __syncthreads();
        if (tid < BP) {
            const int pp2 = tid;
            const int gp2 = p0 + pp2;
            const int b2  = (pp2 < bound) ? bstart : bstart + 1;
            float* op = out + (size_t)gp2 * OUTD;
#pragma unroll
            for (int o = 0; o < OUTD; o++)
                op[o] = g_c[b2 * 8 + o]
                      + part[(o * 4 + 0) * 128 + pp2]
                      + part[(o * 4 + 1) * 128 + pp2]
                      + part[(o * 4 + 2) * 128 + pp2]
                      + part[(o * 4 + 3) * 128 + pp2];
        }
    }
}

// ---------------------------------------------------------------------------
extern "C" void kernel_launch(void* const* d_in, const int* in_sizes, int n_in,
                              void* d_out, int out_size)
{
    const float* coords = (const float*)d_in[0];
    const float* sdf    = (const float*)d_in[1];
    const float* params = (const float*)d_in[2];
    const float* Wb0    = (const float*)d_in[3];
    const float* bb0    = (const float*)d_in[4];
    const float* Wb     = (const float*)d_in[5];
    const float* bb     = (const float*)d_in[6];
    const float* Wbf    = (const float*)d_in[7];
    const float* bbf    = (const float*)d_in[8];
    const float* ab     = (const float*)d_in[9];
    const float* wb     = (const float*)d_in[10];
    const float* Wt0    = (const float*)d_in[11];
    const float* bt0    = (const float*)d_in[12];
    const float* Wt     = (const float*)d_in[13];
    const float* bt     = (const float*)d_in[14];
    const float* Wtf    = (const float*)d_in[15];
    const float* btf    = (const float*)d_in[16];
    const float* at     = (const float*)d_in[17];
    const float* wt     = (const float*)d_in[18];
    float* out = (float*)d_out;

    static int smem_set = 0;
    const int smem_bytes = (HID * XSTRIDE + WROWS * WSTRIDE) * sizeof(float); // 101376
    if (!smem_set) {
        cudaFuncSetAttribute(trunk_kernel,
                             cudaFuncAttributeMaxDynamicSharedMemorySize,
                             smem_bytes);
        smem_set = 1;
    }

    branch_kernel<<<NB, 512>>>(params, Wb0, bb0, Wb, bb, Wbf, bbf, ab, wb,
                               Wtf, btf);
    trunk_kernel<<<LTOT / BP, 512, smem_bytes>>>(coords, sdf, Wt0, bt0,
                                                 Wt, bt, at, wt, out);
}